// round 12
// baseline (speedup 1.0000x reference)
#include <cuda_runtime.h>
#include <cuda_bf16.h>
#include <cstdint>

// OctonionFanoCoherence (composition-algebra form, verified rel_err ~1.7e-6):
//   ||x̂i*x̂j - x̂k||^2 = 2 - 2*dot(omul(xi,xj), xk)*inv_i*inv_j*inv_k
//   avg_error = 2 - (2/7)*sum_l dot_l ; phi = clip(-log(avg+1e-8)*exp(ls),0,10)
//
// R12: bulk staging. Each warp owns 63 elements (14112B, 16B-multiple) and
// fetches its whole slice with ONE cp.async.bulk (UBLKCP) completed on a
// per-warp mbarrier — 1 issue op instead of 28 cp.async, and large
// contiguous DRAM-side requests. Warp-autonomous: no __syncthreads.

#define TPB      128
#define WARPS    (TPB / 32)
#define WELEMS   63                       // elements per warp slice
#define ELEM_F4  14                       // 14 float4 = 56 floats per element
#define WTILE_F4 (WELEMS * ELEM_F4)       // 882 float4 = 14112 B

// ---- VERIFIED rounds 1/3/4/7/10/11 — verbatim, do not re-derive ----
__device__ __forceinline__ void qmul(const float* p, const float* q, float* r) {
    r[0] = p[0]*q[0] - p[1]*q[1] - p[2]*q[2] - p[3]*q[3];
    r[1] = p[0]*q[1] + p[1]*q[0] + p[2]*q[3] - p[3]*q[2];
    r[2] = p[0]*q[2] - p[1]*q[3] + p[2]*q[0] + p[3]*q[1];
    r[3] = p[0]*q[3] + p[1]*q[2] - p[2]*q[1] + p[3]*q[0];
}
__device__ __forceinline__ void omul_v(const float* x, const float* y, float* z) {
    const float* a1 = x;     const float* a2 = x + 4;
    const float* b1 = y;     const float* b2 = y + 4;
    float t1[4], t2[4];
    qmul(a1, b1, t1);
    float cb2[4] = { b2[0], -b2[1], -b2[2], -b2[3] };
    qmul(cb2, a2, t2);
    z[0] = t1[0] - t2[0]; z[1] = t1[1] - t2[1];
    z[2] = t1[2] - t2[2]; z[3] = t1[3] - t2[3];
    qmul(b2, a1, t1);
    float cb1[4] = { b1[0], -b1[1], -b1[2], -b1[3] };
    qmul(a2, cb1, t2);
    z[4] = t1[0] + t2[0]; z[5] = t1[1] + t2[1];
    z[6] = t1[2] + t2[2]; z[7] = t1[3] + t2[3];
}

// Per-element body: read 56 floats from smem (AoS slot), return phi.
__device__ __forceinline__ float oct_phi(const float4* ebase, float esens) {
    float x[56];
#pragma unroll
    for (int i = 0; i < ELEM_F4; ++i) {
        float4 v = ebase[i];
        x[4*i + 0] = v.x; x[4*i + 1] = v.y;
        x[4*i + 2] = v.z; x[4*i + 3] = v.w;
    }
    float inv[7];
#pragma unroll
    for (int l = 0; l < 7; ++l) {
        float acc = 0.f;
#pragma unroll
        for (int c = 0; c < 8; ++c)
            acc = fmaf(x[l*8 + c], x[l*8 + c], acc);
        inv[l] = rsqrtf(fmaxf(acc, 1e-24f));   // == 1/max(||x||,1e-12)
    }
    float sacc = 0.f;
#pragma unroll
    for (int l = 0; l < 7; ++l) {
        const int i = l, j = (l + 1) % 7, k = (l + 3) % 7;
        float p[8];
        omul_v(&x[i*8], &x[j*8], p);
        const float* xk = &x[k*8];
        float d = 0.f;
#pragma unroll
        for (int c = 0; c < 8; ++c)
            d = fmaf(p[c], xk[c], d);
        sacc = fmaf(d, inv[i] * inv[j] * inv[k], sacc);
    }
    float avg = fmaf(sacc, -2.0f / 7.0f, 2.0f);   // avg_error = 2 - (2/7)*s
    float phi = -__logf(avg + 1e-8f) * esens;
    return fminf(fmaxf(phi, 0.0f), 10.0f);
}
// -------------------------------------------------------------

__global__ void __launch_bounds__(TPB, 4)
oct_fano_kernel(const float* __restrict__ in,
                const float* __restrict__ log_sens,
                float* __restrict__ out,
                int B)
{
    __shared__ float4 s[WARPS][WTILE_F4];                 // 4 * 14112 = 56448 B
    __shared__ __align__(8) unsigned long long mbar[WARPS];

    const int lane = threadIdx.x & 31;
    const int wid  = threadIdx.x >> 5;
    const long long warpBase =
        ((long long)blockIdx.x * WARPS + wid) * WELEMS;   // first element

    const int elems = (int)min((long long)WELEMS, (long long)B - warpBase);
    if (elems <= 0) return;                                // idle tail warp
    const uint32_t bytes = (uint32_t)elems * 224u;         // 224 = 14*16, 16B multiple

    const uint32_t mb = (uint32_t)__cvta_generic_to_shared(&mbar[wid]);
    const uint32_t dst = (uint32_t)__cvta_generic_to_shared(&s[wid][0]);
    const float* src = in + warpBase * 56;

    // ---- one-shot per-warp mbarrier + single bulk copy of the slice ----
    if (lane == 0) {
        asm volatile("mbarrier.init.shared.b64 [%0], %1;"
                     :: "r"(mb), "r"(1u) : "memory");
    }
    __syncwarp();          // init visible to all lanes before wait / issue
    if (lane == 0) {
        asm volatile("mbarrier.arrive.expect_tx.shared.b64 _, [%0], %1;"
                     :: "r"(mb), "r"(bytes) : "memory");
        asm volatile("cp.async.bulk.shared::cta.global.mbarrier::complete_tx::bytes"
                     " [%0], [%1], %2, [%3];"
                     :: "r"(dst), "l"(src), "r"(bytes), "r"(mb) : "memory");
    }

    const float esens = __expf(__ldg(log_sens));   // MUFU, overlaps the copy

    // ---- wait for the slice (parity 0, acquire) ----
    {
        uint32_t done;
        asm volatile(
            "{\n\t"
            ".reg .pred p;\n\t"
            "mbarrier.try_wait.parity.acquire.cta.shared::cta.b64 p, [%1], %2;\n\t"
            "selp.b32 %0, 1, 0, p;\n\t"
            "}"
            : "=r"(done) : "r"(mb), "r"(0u) : "memory");
        if (!done) {
            asm volatile(
                "{\n\t"
                ".reg .pred P1;\n\t"
                "WAIT_LOOP_%=:\n\t"
                "mbarrier.try_wait.parity.acquire.cta.shared::cta.b64 P1, [%0], %1, 0x989680;\n\t"
                "@P1 bra.uni WAIT_DONE_%=;\n\t"
                "bra.uni WAIT_LOOP_%=;\n\t"
                "WAIT_DONE_%=:\n\t"
                "}"
                :: "r"(mb), "r"(0u) : "memory");
        }
    }

    // ---- compute: element e0 = lane, e1 = 32 + lane ----
    if (lane < elems) {
        float phi = oct_phi(&s[wid][lane * ELEM_F4], esens);
        out[warpBase + lane] = phi;
    }
    if (32 + lane < elems) {
        float phi = oct_phi(&s[wid][(32 + lane) * ELEM_F4], esens);
        out[warpBase + 32 + lane] = phi;
    }
}

extern "C" void kernel_launch(void* const* d_in, const int* in_sizes, int n_in,
                              void* d_out, int out_size)
{
    const float* colony   = (const float*)d_in[0];   // [B, 7, 8] fp32
    const float* log_sens = (const float*)d_in[1];   // scalar fp32
    float* out = (float*)d_out;                      // [B] fp32

    int B = in_sizes[0] / 56;
    long long per_cta = (long long)WELEMS * WARPS;   // 252 elements per CTA
    int blocks = (int)((B + per_cta - 1) / per_cta);
    oct_fano_kernel<<<blocks, TPB>>>(colony, log_sens, out, B);
}

// round 13
// speedup vs baseline: 1.0502x; 1.0502x over previous
#include <cuda_runtime.h>
#include <cuda_bf16.h>
#include <cstdint>

// OctonionFanoCoherence:
//   avg_error = 2 - (2/7)*s,  s = sum_l dot(omul(xi,xj), xk)*inv_i*inv_j*inv_k
//   phi = clip(-log(avg+1e-8)*exp(ls), 0, 10)
// KEY: phi == 0 exactly iff avg >= 1 iff s <= 3.5. Fast bf16x2 path computes
// s for TWO elements per op; if s_fast <= 3.0 (>=0.4 safety margin vs worst
// bf16 error ~0.1) output is provably 0. Otherwise exact f32 recompute.
// Staging: R12 bulk-copy (one cp.async.bulk per warp slice, per-warp mbarrier).

#define TPB      128
#define WARPS    (TPB / 32)
#define WELEMS   63                       // elements per warp slice
#define ELEM_F4  14                       // 14 float4 = 56 floats per element
#define WTILE_F4 (WELEMS * ELEM_F4)       // 882 float4 = 14112 B

typedef __nv_bfloat162 b2;

// ---- VERIFIED f32 path (rounds 1/3/4/7/10-12) — verbatim ----
__device__ __forceinline__ void qmul(const float* p, const float* q, float* r) {
    r[0] = p[0]*q[0] - p[1]*q[1] - p[2]*q[2] - p[3]*q[3];
    r[1] = p[0]*q[1] + p[1]*q[0] + p[2]*q[3] - p[3]*q[2];
    r[2] = p[0]*q[2] - p[1]*q[3] + p[2]*q[0] + p[3]*q[1];
    r[3] = p[0]*q[3] + p[1]*q[2] - p[2]*q[1] + p[3]*q[0];
}
__device__ __forceinline__ void omul_v(const float* x, const float* y, float* z) {
    const float* a1 = x;     const float* a2 = x + 4;
    const float* b1 = y;     const float* b2_ = y + 4;
    float t1[4], t2[4];
    qmul(a1, b1, t1);
    float cb2[4] = { b2_[0], -b2_[1], -b2_[2], -b2_[3] };
    qmul(cb2, a2, t2);
    z[0] = t1[0] - t2[0]; z[1] = t1[1] - t2[1];
    z[2] = t1[2] - t2[2]; z[3] = t1[3] - t2[3];
    qmul(b2_, a1, t1);
    float cb1[4] = { b1[0], -b1[1], -b1[2], -b1[3] };
    qmul(a2, cb1, t2);
    z[4] = t1[0] + t2[0]; z[5] = t1[1] + t2[1];
    z[6] = t1[2] + t2[2]; z[7] = t1[3] + t2[3];
}
__device__ __noinline__ float oct_phi(const float4* ebase, float esens) {
    float x[56];
#pragma unroll
    for (int i = 0; i < ELEM_F4; ++i) {
        float4 v = ebase[i];
        x[4*i + 0] = v.x; x[4*i + 1] = v.y;
        x[4*i + 2] = v.z; x[4*i + 3] = v.w;
    }
    float inv[7];
#pragma unroll
    for (int l = 0; l < 7; ++l) {
        float acc = 0.f;
#pragma unroll
        for (int c = 0; c < 8; ++c)
            acc = fmaf(x[l*8 + c], x[l*8 + c], acc);
        inv[l] = rsqrtf(fmaxf(acc, 1e-24f));
    }
    float sacc = 0.f;
#pragma unroll
    for (int l = 0; l < 7; ++l) {
        const int i = l, j = (l + 1) % 7, k = (l + 3) % 7;
        float p[8];
        omul_v(&x[i*8], &x[j*8], p);
        const float* xk = &x[k*8];
        float d = 0.f;
#pragma unroll
        for (int c = 0; c < 8; ++c)
            d = fmaf(p[c], xk[c], d);
        sacc = fmaf(d, inv[i] * inv[j] * inv[k], sacc);
    }
    float avg = fmaf(sacc, -2.0f / 7.0f, 2.0f);
    float phi = -__logf(avg + 1e-8f) * esens;
    return fminf(fmaxf(phi, 0.0f), 10.0f);
}
// -------------------------------------------------------------

// ---- bf16x2 fast path: same sign structure as verified qmul ----
//  r0 = p0q0 - p1q1 - p2q2 - p3q3 ; r1 = p0q1 + p1q0 + p2q3 - p3q2
//  r2 = p0q2 - p1q3 + p2q0 + p3q1 ; r3 = p0q3 + p1q2 - p2q1 + p3q0
__device__ __forceinline__ void qmul_b(const b2* p, const b2* q, b2* r) {
    b2 n, a;
    n = __hfma2(p[1], q[1], __hfma2(p[2], q[2], __hmul2(p[3], q[3])));
    r[0] = __hfma2(p[0], q[0], __hneg2(n));
    a = __hfma2(p[1], q[0], __hfma2(p[2], q[3], __hmul2(p[0], q[1])));
    r[1] = __hfma2(__hneg2(p[3]), q[2], a);
    a = __hfma2(p[2], q[0], __hfma2(p[3], q[1], __hmul2(p[0], q[2])));
    r[2] = __hfma2(__hneg2(p[1]), q[3], a);
    a = __hfma2(p[1], q[2], __hfma2(p[3], q[0], __hmul2(p[0], q[3])));
    r[3] = __hfma2(__hneg2(p[2]), q[1], a);
}
// omul_b mirrors verified omul structure: z1 = a1b1 - conj(b2)a2, z2 = b2a1 + a2conj(b1)
__device__ __forceinline__ void omul_b(const b2* x, const b2* y, b2* z) {
    const b2* a1 = x;     const b2* a2 = x + 4;
    const b2* b1 = y;     const b2* b2q = y + 4;
    b2 t1[4], t2[4];
    qmul_b(a1, b1, t1);
    b2 cb2[4] = { b2q[0], __hneg2(b2q[1]), __hneg2(b2q[2]), __hneg2(b2q[3]) };
    qmul_b(cb2, a2, t2);
    z[0] = __hsub2(t1[0], t2[0]); z[1] = __hsub2(t1[1], t2[1]);
    z[2] = __hsub2(t1[2], t2[2]); z[3] = __hsub2(t1[3], t2[3]);
    qmul_b(b2q, a1, t1);
    b2 cb1[4] = { b1[0], __hneg2(b1[1]), __hneg2(b1[2]), __hneg2(b1[3]) };
    qmul_b(a2, cb1, t2);
    z[4] = __hadd2(t1[0], t2[0]); z[5] = __hadd2(t1[1], t2[1]);
    z[6] = __hadd2(t1[2], t2[2]); z[7] = __hadd2(t1[3], t2[3]);
}
// -------------------------------------------------------------

__global__ void __launch_bounds__(TPB, 4)
oct_fano_kernel(const float* __restrict__ in,
                const float* __restrict__ log_sens,
                float* __restrict__ out,
                int B)
{
    __shared__ float4 s[WARPS][WTILE_F4];                 // 4 * 14112 = 56448 B
    __shared__ __align__(8) unsigned long long mbar[WARPS];

    const int lane = threadIdx.x & 31;
    const int wid  = threadIdx.x >> 5;
    const long long warpBase =
        ((long long)blockIdx.x * WARPS + wid) * WELEMS;

    const int elems = (int)min((long long)WELEMS, (long long)B - warpBase);
    if (elems <= 0) return;
    const uint32_t bytes = (uint32_t)elems * 224u;        // 14*16 per element

    const uint32_t mb  = (uint32_t)__cvta_generic_to_shared(&mbar[wid]);
    const uint32_t dst = (uint32_t)__cvta_generic_to_shared(&s[wid][0]);
    const float* src = in + warpBase * 56;

    if (lane == 0) {
        asm volatile("mbarrier.init.shared.b64 [%0], %1;"
                     :: "r"(mb), "r"(1u) : "memory");
    }
    __syncwarp();
    if (lane == 0) {
        asm volatile("mbarrier.arrive.expect_tx.shared.b64 _, [%0], %1;"
                     :: "r"(mb), "r"(bytes) : "memory");
        asm volatile("cp.async.bulk.shared::cta.global.mbarrier::complete_tx::bytes"
                     " [%0], [%1], %2, [%3];"
                     :: "r"(dst), "l"(src), "r"(bytes), "r"(mb) : "memory");
    }

    const float esens = __expf(__ldg(log_sens));

    {   // wait parity 0, acquire
        uint32_t done;
        asm volatile(
            "{\n\t.reg .pred p;\n\t"
            "mbarrier.try_wait.parity.acquire.cta.shared::cta.b64 p, [%1], %2;\n\t"
            "selp.b32 %0, 1, 0, p;\n\t}"
            : "=r"(done) : "r"(mb), "r"(0u) : "memory");
        if (!done) {
            asm volatile(
                "{\n\t.reg .pred P1;\n\t"
                "WAIT_LOOP_%=:\n\t"
                "mbarrier.try_wait.parity.acquire.cta.shared::cta.b64 P1, [%0], %1, 0x989680;\n\t"
                "@P1 bra.uni WAIT_DONE_%=;\n\t"
                "bra.uni WAIT_LOOP_%=;\n\t"
                "WAIT_DONE_%=:\n\t}"
                :: "r"(mb), "r"(0u) : "memory");
        }
    }

    // ---- Fast bf16x2 path: element pair (lane, lane+32), clamped for tail ----
    const int e0i = min(lane, elems - 1);
    const int e1i = min(32 + lane, elems - 1);
    const float4* e0p = &s[wid][e0i * ELEM_F4];
    const float4* e1p = &s[wid][e1i * ELEM_F4];

    b2 xb[56];
#pragma unroll
    for (int i = 0; i < ELEM_F4; ++i) {
        float4 a = e0p[i];
        float4 b = e1p[i];
        xb[4*i + 0] = __floats2bfloat162_rn(a.x, b.x);   // low = e0, high = e1
        xb[4*i + 1] = __floats2bfloat162_rn(a.y, b.y);
        xb[4*i + 2] = __floats2bfloat162_rn(a.z, b.z);
        xb[4*i + 3] = __floats2bfloat162_rn(a.w, b.w);
    }

    b2 invb[7];
#pragma unroll
    for (int l = 0; l < 7; ++l) {
        b2 acc = __hmul2(xb[l*8], xb[l*8]);
#pragma unroll
        for (int c = 1; c < 8; ++c)
            acc = __hfma2(xb[l*8 + c], xb[l*8 + c], acc);
        float n0 = __low2float(acc), n1 = __high2float(acc);
        invb[l] = __floats2bfloat162_rn(rsqrtf(fmaxf(n0, 1e-24f)),
                                        rsqrtf(fmaxf(n1, 1e-24f)));
    }

    b2 sacc = __float2bfloat162_rn(0.0f);
#pragma unroll
    for (int l = 0; l < 7; ++l) {
        const int i = l, j = (l + 1) % 7, k = (l + 3) % 7;
        b2 p[8];
        omul_b(&xb[i*8], &xb[j*8], p);
        const b2* xk = &xb[k*8];
        b2 d = __hmul2(p[0], xk[0]);
#pragma unroll
        for (int c = 1; c < 8; ++c)
            d = __hfma2(p[c], xk[c], d);
        b2 w = __hmul2(__hmul2(invb[i], invb[j]), invb[k]);
        sacc = __hfma2(d, w, sacc);
    }

    float s0 = __low2float(sacc);
    float s1 = __high2float(sacc);

    // phi == 0 exactly iff s <= 3.5. bf16 |error| < 0.4 -> s_fast <= 3.0 proves it.
    float phi0 = 0.0f, phi1 = 0.0f;
    if (s0 > 3.0f) phi0 = oct_phi(&s[wid][e0i * ELEM_F4], esens);   // exact f32
    if (s1 > 3.0f) phi1 = oct_phi(&s[wid][e1i * ELEM_F4], esens);

    if (lane < elems)      out[warpBase + lane]      = phi0;
    if (32 + lane < elems) out[warpBase + 32 + lane] = phi1;
}

extern "C" void kernel_launch(void* const* d_in, const int* in_sizes, int n_in,
                              void* d_out, int out_size)
{
    const float* colony   = (const float*)d_in[0];   // [B, 7, 8] fp32
    const float* log_sens = (const float*)d_in[1];   // scalar fp32
    float* out = (float*)d_out;                      // [B] fp32

    int B = in_sizes[0] / 56;
    long long per_cta = (long long)WELEMS * WARPS;   // 252 elements per CTA
    int blocks = (int)((B + per_cta - 1) / per_cta);
    oct_fano_kernel<<<blocks, TPB>>>(colony, log_sens, out, B);
}